// round 9
// baseline (speedup 1.0000x reference)
#include <cuda_runtime.h>
#include <cuda_bf16.h>

// Single-pass WKV scan, decoupled lookback, float4 (LDG.128) loads.
//
// Block = 256 threads = 8 float4-channel-groups (32 channels) x 32 sub-
// segments of 4 timesteps -> block covers 128 timesteps; chain = 16 hops.
//
// Thread-local normalized scan (decay product cancels in out = b/a):
//   cw_i = sum w ; e_i = exp(k_i - cw_i) ; ah_i = sum e ; bh_i = sum e*v
// Sub-segment map: a_out = P*a_in + P*aa, P = exp(cw_end).
// 32 threads compose the 32 maps per channel (exclusive prefixes are linear
// in the incoming state -> all intra-block work precedes the lookback).
//
// Flags are self-cleaning: consumer (s+1) resets flag[s] after reading; the
// last segment publishes nothing -> flags all-zero after every replay, no
// reset kernel needed.

#define BATCH  16
#define TLEN   2048
#define DIM    1024
#define CHAN   (BATCH * DIM)       // 16384
#define NCH    32                  // channels per block
#define NCHV   8                   // float4 channel groups per block
#define NSUB   32                  // sub-segments per block
#define SUBSEG 4                   // timesteps per thread
#define SEGT   (NSUB * SUBSEG)     // 128 timesteps per block
#define NSEG   (TLEN / SEGT)       // 16 global segments
#define NCG    (CHAN / NCH)        // 512 channel groups
#define BLKT   (NCHV * NSUB)       // 256 threads

__device__ float    g_prefA[NSEG * CHAN];
__device__ float    g_prefB[NSEG * CHAN];
__device__ unsigned g_flag [NSEG * NCG];   // zero-init; self-cleaning

__global__ __launch_bounds__(BLKT, 3)
void wkv_fused(const float* __restrict__ K,
               const float* __restrict__ V,
               const float* __restrict__ W,
               float* __restrict__ O) {
    const int s    = blockIdx.x / NCG;      // global segment (segment-major)
    const int cg   = blockIdx.x % NCG;      // channel group
    const int tid  = threadIdx.x;
    const int chv  = tid & (NCHV - 1);      // float4 channel group 0..7
    const int sub  = tid >> 3;              // sub-segment 0..31
    const int c0   = cg * NCH + chv * 4;    // first of 4 channels
    const int b    = c0 >> 10;              // / DIM   (NCH divides DIM)
    const int d    = c0 & (DIM - 1);        // % DIM

    __shared__ float sP [NSUB][NCH], sQa[NSUB][NCH], sQb[NSUB][NCH];
    __shared__ float sBt[NSUB][NCH], sAl[NSUB][NCH], sBl[NSUB][NCH];
    __shared__ float sA0[NCH], sB0[NCH];

    const int t0 = s * SEGT + sub * SUBSEG;
    const size_t base = (size_t)b * TLEN * DIM + (size_t)t0 * DIM + d;
    const float* kp = K + base;
    const float* vp = V + base;
    const float* wp = W + base;
    float*       op = O + base;

    // ---- thread-local normalized scan: 4 steps x 4 channels, float4 ----
    float cw[4] = {0,0,0,0}, aa[4] = {0,0,0,0}, bb[4] = {0,0,0,0};
    float ah[SUBSEG][4], bh[SUBSEG][4];
#pragma unroll
    for (int i = 0; i < SUBSEG; ++i) {
        const float4 k4 = *(const float4*)(kp + i * DIM);
        const float4 v4 = *(const float4*)(vp + i * DIM);
        const float4 w4 = *(const float4*)(wp + i * DIM);
        const float kk[4] = {k4.x, k4.y, k4.z, k4.w};
        const float vv[4] = {v4.x, v4.y, v4.z, v4.w};
        const float ww[4] = {w4.x, w4.y, w4.z, w4.w};
#pragma unroll
        for (int j = 0; j < 4; ++j) {
            cw[j] += ww[j];
            const float e = __expf(kk[j] - cw[j]);
            aa[j] += e;
            bb[j] = fmaf(e, vv[j], bb[j]);
            ah[i][j] = aa[j];
            bh[i][j] = bb[j];
        }
    }
#pragma unroll
    for (int j = 0; j < 4; ++j) {
        const float P = __expf(cw[j]);
        sP [sub][chv * 4 + j] = P;
        sQa[sub][chv * 4 + j] = P * aa[j];
        sQb[sub][chv * 4 + j] = P * bb[j];
    }
    __syncthreads();

    // ---- 32 threads: compose 32 sub-segment maps per channel, lookback,
    //      publish ----
    if (tid < NCH) {
        float beta = 1.0f, alA = 0.0f, alB = 0.0f;
#pragma unroll
        for (int j = 0; j < NSUB; ++j) {
            sBt[j][tid] = beta;
            sAl[j][tid] = alA;
            sBl[j][tid] = alB;
            const float p = sP[j][tid];
            beta = p * beta;
            alA  = fmaf(p, alA, sQa[j][tid]);
            alB  = fmaf(p, alB, sQb[j][tid]);
        }

        float a0 = 0.0f, b0 = 0.0f;
        if (s > 0) {
            volatile unsigned* f = &g_flag[(s - 1) * NCG + cg];
            while (*f == 0u) __nanosleep(40);
            __threadfence();   // acquire
            a0 = g_prefA[(size_t)(s - 1) * CHAN + cg * NCH + tid];
            b0 = g_prefB[(size_t)(s - 1) * CHAN + cg * NCH + tid];
            if (tid == 0) atomicExch(&g_flag[(s - 1) * NCG + cg], 0u); // self-clean
        }
        sA0[tid] = a0;
        sB0[tid] = b0;

        if (s < NSEG - 1) {    // last segment has no consumer
            g_prefA[(size_t)s * CHAN + cg * NCH + tid] = fmaf(beta, a0, alA);
            g_prefB[(size_t)s * CHAN + cg * NCH + tid] = fmaf(beta, b0, alB);
            __threadfence();   // release
            __syncwarp(0xFFFFFFFFu);
            if (tid == 0) atomicExch(&g_flag[s * NCG + cg], 1u);
        }
    }
    __syncthreads();

    // ---- outputs: float4 stores ----
    float Ain[4], Bin[4];
#pragma unroll
    for (int j = 0; j < 4; ++j) {
        const int ch = chv * 4 + j;
        const float beta = sBt[sub][ch];
        Ain[j] = fmaf(beta, sA0[ch], sAl[sub][ch]);
        Bin[j] = fmaf(beta, sB0[ch], sBl[sub][ch]);
    }
#pragma unroll
    for (int i = 0; i < SUBSEG; ++i) {
        float4 o4;
        o4.x = __fdividef(Bin[0] + bh[i][0], Ain[0] + ah[i][0]);
        o4.y = __fdividef(Bin[1] + bh[i][1], Ain[1] + ah[i][1]);
        o4.z = __fdividef(Bin[2] + bh[i][2], Ain[2] + ah[i][2]);
        o4.w = __fdividef(Bin[3] + bh[i][3], Ain[3] + ah[i][3]);
        *(float4*)(op + i * DIM) = o4;
    }
}

extern "C" void kernel_launch(void* const* d_in, const int* in_sizes, int n_in,
                              void* d_out, int out_size) {
    const float* K = (const float*)d_in[0];
    const float* V = (const float*)d_in[1];
    const float* W = (const float*)d_in[2];
    float*       O = (float*)d_out;

    wkv_fused<<<NSEG * NCG, BLKT>>>(K, V, W, O);   // 8192 blocks, segment-major
}

// round 10
// speedup vs baseline: 1.0480x; 1.0480x over previous
#include <cuda_runtime.h>
#include <cuda_bf16.h>

// Single-pass WKV scan, decoupled lookback, intra-block sub-segment scan.
// R9: R6 structure + FRONT-BATCHED loads (48 LDGs issued before any compute)
// to lift in-flight bytes/SM ~2.6x above the Little's-law requirement.
// Flags self-cleaning (consumer resets; last segment never publishes) -> no
// reset kernel.
//
// Block = 256 threads = 32 channels x 8 sub-segments of 16 timesteps.
// Thread-local normalized scan (decay product cancels in out = b/a):
//   cw_i = sum w ; e_i = exp(k_i - cw_i) ; ah_i = sum e ; bh_i = sum e*v
// Sub-segment map: a_out = P*a_in + P*aa, P = exp(cw_end). Warp 0 composes
// the 8 maps per channel; exclusive prefixes are linear in the incoming
// state, so all heavy work precedes the lookback wait.

#define BATCH  16
#define TLEN   2048
#define DIM    1024
#define CHAN   (BATCH * DIM)       // 16384
#define NCH    32                  // channels per block
#define NSUB   8                   // sub-segments per block
#define SUBSEG 16                  // timesteps per thread
#define SEGT   (NSUB * SUBSEG)     // 128 timesteps per block
#define NSEG   (TLEN / SEGT)       // 16 global segments
#define NCG    (CHAN / NCH)        // 512 channel groups
#define BLKT   (NCH * NSUB)        // 256 threads

__device__ float    g_prefA[NSEG * CHAN];
__device__ float    g_prefB[NSEG * CHAN];
__device__ unsigned g_flag [NSEG * NCG];   // zero-init; self-cleaning

__global__ __launch_bounds__(BLKT, 4)
void wkv_fused(const float* __restrict__ K,
               const float* __restrict__ V,
               const float* __restrict__ W,
               float* __restrict__ O) {
    const int s    = blockIdx.x / NCG;      // global segment (segment-major)
    const int cg   = blockIdx.x % NCG;      // channel group
    const int tid  = threadIdx.x;
    const int lane = tid & (NCH - 1);       // channel within group
    const int sub  = tid >> 5;              // sub-segment 0..7
    const int c    = cg * NCH + lane;       // global channel
    const int b    = c >> 10;               // / DIM
    const int d    = c & (DIM - 1);         // % DIM

    __shared__ float sP [NSUB][NCH], sQa[NSUB][NCH], sQb[NSUB][NCH];
    __shared__ float sBt[NSUB][NCH], sAl[NSUB][NCH], sBl[NSUB][NCH];
    __shared__ float sA0[NCH], sB0[NCH];

    const int t0 = s * SEGT + sub * SUBSEG;
    const size_t base = (size_t)b * TLEN * DIM + (size_t)t0 * DIM + d;
    const float* kp = K + base;
    const float* vp = V + base;
    const float* wp = W + base;
    float*       op = O + base;

    // ---- front-batched loads: 48 independent LDGs before any compute ----
    float wb[SUBSEG], kb[SUBSEG], vb[SUBSEG];
#pragma unroll
    for (int i = 0; i < SUBSEG; ++i) wb[i] = wp[i * DIM];
#pragma unroll
    for (int i = 0; i < SUBSEG; ++i) kb[i] = kp[i * DIM];
#pragma unroll
    for (int i = 0; i < SUBSEG; ++i) vb[i] = vp[i * DIM];

    // ---- normalized local scan; reuse kb -> ah, vb -> bh in place ----
    float cw = 0.0f, aa = 0.0f, bb = 0.0f;
#pragma unroll
    for (int i = 0; i < SUBSEG; ++i) {
        cw += wb[i];
        const float e = __expf(kb[i] - cw);
        aa += e;
        bb = fmaf(e, vb[i], bb);
        kb[i] = aa;      // ah
        vb[i] = bb;      // bh
    }
    const float P = __expf(cw);
    sP [sub][lane] = P;
    sQa[sub][lane] = P * aa;
    sQb[sub][lane] = P * bb;
    __syncthreads();

    // ---- warp 0: compose 8 maps per channel, lookback, publish ----
    if (tid < NCH) {
        float beta = 1.0f, alA = 0.0f, alB = 0.0f;
#pragma unroll
        for (int j = 0; j < NSUB; ++j) {
            sBt[j][tid] = beta;
            sAl[j][tid] = alA;
            sBl[j][tid] = alB;
            const float p = sP[j][tid];
            beta = p * beta;
            alA  = fmaf(p, alA, sQa[j][tid]);
            alB  = fmaf(p, alB, sQb[j][tid]);
        }

        float a0 = 0.0f, b0 = 0.0f;
        if (s > 0) {
            volatile unsigned* f = &g_flag[(s - 1) * NCG + cg];
            while (*f == 0u) __nanosleep(40);
            __threadfence();   // acquire
            a0 = g_prefA[(size_t)(s - 1) * CHAN + c];
            b0 = g_prefB[(size_t)(s - 1) * CHAN + c];
            if (tid == 0) atomicExch(&g_flag[(s - 1) * NCG + cg], 0u); // self-clean
        }
        sA0[tid] = a0;
        sB0[tid] = b0;

        if (s < NSEG - 1) {    // last segment has no consumer
            g_prefA[(size_t)s * CHAN + c] = fmaf(beta, a0, alA);
            g_prefB[(size_t)s * CHAN + c] = fmaf(beta, b0, alB);
            __threadfence();   // release
            __syncwarp(0xFFFFFFFFu);
            if (tid == 0) atomicExch(&g_flag[s * NCG + cg], 1u);
        }
    }
    __syncthreads();

    // ---- outputs ----
    const float beta = sBt[sub][lane];
    const float A_in = fmaf(beta, sA0[lane], sAl[sub][lane]);
    const float B_in = fmaf(beta, sB0[lane], sBl[sub][lane]);
#pragma unroll
    for (int i = 0; i < SUBSEG; ++i)
        op[i * DIM] = __fdividef(B_in + vb[i], A_in + kb[i]);
}

extern "C" void kernel_launch(void* const* d_in, const int* in_sizes, int n_in,
                              void* d_out, int out_size) {
    const float* K = (const float*)d_in[0];
    const float* V = (const float*)d_in[1];
    const float* W = (const float*)d_in[2];
    float*       O = (float*)d_out;

    wkv_fused<<<NSEG * NCG, BLKT>>>(K, V, W, O);   // 8192 blocks, segment-major
}